// round 8
// baseline (speedup 1.0000x reference)
#include <cuda_runtime.h>
#include <cuda_bf16.h>

#define NNODES 100000
#define NEDGES 1600000
#define DH 128
#define DOUT 64
#define BN_EPS 1e-5f

#define TM 64                      // rows per GEMM block
#define GEMM_THREADS 256
#define GEMM_SMEM ((DH*DH + TM*DH) * sizeof(float))   // 96 KB
#define GRID_GEMM ((NNODES + TM - 1) / TM)

// ---------------- device scratch ----------------
__device__ float g_h[(long)NNODES * DH];     // GEMM output (h = xW)
__device__ float g_agg[(long)NNODES * DH];   // aggregation buffer
__device__ float g_s[NNODES];                // per-src edge-weight sums
__device__ float g_stats[2 * DH];            // column sum / sumsq
__device__ float g_scale[DH];                // BN fused scale
__device__ float g_shift[DH];                // BN fused shift
__device__ float g_t[DH];                    // s^T x1

// ---------------- zero kernels ----------------
__global__ void zero_agg_kernel() {
    const long n4 = (long)NNODES * DH / 4;
    float4 z = make_float4(0.f, 0.f, 0.f, 0.f);
    for (long i = (long)blockIdx.x * blockDim.x + threadIdx.x; i < n4;
         i += (long)gridDim.x * blockDim.x)
        ((float4*)g_agg)[i] = z;
}

__global__ void zero_small_kernel() {
    int t = threadIdx.x;
    if (t < 2 * DH)      g_stats[t] = 0.f;
    else                 g_t[t - 2 * DH] = 0.f;   // t in [256, 384)
}

__global__ void zero_s_kernel() {
    for (int i = blockIdx.x * blockDim.x + threadIdx.x; i < NNODES;
         i += gridDim.x * blockDim.x)
        g_s[i] = 0.f;
}

// ---------------- GEMM: Y(g_h) = X @ W, optionally X = relu(bn(g_agg)) -------
// mode 0: X = Xext (raw), mode 1: X = relu(g_agg*scale+shift)
__global__ void gemm_kernel(const float* __restrict__ Xext,
                            const float* __restrict__ W,
                            int n_rows, int mode) {
    extern __shared__ float smem[];
    float* ws = smem;            // DH*DH
    float* xs = smem + DH * DH;  // TM*DH

    const int tid = threadIdx.x;
    const float* X = (mode == 0) ? Xext : g_agg;

    // load W (16384 floats) via float4
    for (int i = tid; i < DH * DH / 4; i += GEMM_THREADS)
        ((float4*)ws)[i] = ((const float4*)W)[i];

    const int row0 = blockIdx.x * TM;
    // load X tile (TM x DH) via float4, with fused BN+ReLU for mode 1
    for (int i = tid; i < TM * DH / 4; i += GEMM_THREADS) {
        int r  = i / (DH / 4);
        int c4 = i % (DH / 4);
        float4 v = make_float4(0.f, 0.f, 0.f, 0.f);
        if (row0 + r < n_rows) {
            v = ((const float4*)(X + (long)(row0 + r) * DH))[c4];
            if (mode) {
                int c = c4 * 4;
                v.x = fmaxf(0.f, fmaf(v.x, g_scale[c + 0], g_shift[c + 0]));
                v.y = fmaxf(0.f, fmaf(v.y, g_scale[c + 1], g_shift[c + 1]));
                v.z = fmaxf(0.f, fmaf(v.z, g_scale[c + 2], g_shift[c + 2]));
                v.w = fmaxf(0.f, fmaf(v.w, g_scale[c + 3], g_shift[c + 3]));
            }
        }
        ((float4*)xs)[i] = v;
    }
    __syncthreads();

    const int lane = tid & 31;
    const int warp = tid >> 5;          // 8 warps; warp handles 8 rows
    const float* xbase = xs + warp * 8 * DH;

    float acc[8][4];
#pragma unroll
    for (int i = 0; i < 8; i++) {
        acc[i][0] = 0.f; acc[i][1] = 0.f; acc[i][2] = 0.f; acc[i][3] = 0.f;
    }

#pragma unroll 8
    for (int k = 0; k < DH; k++) {
        float4 wv = *(const float4*)(ws + k * DH + lane * 4);
#pragma unroll
        for (int i = 0; i < 8; i++) {
            float xv = xbase[i * DH + k];   // warp-broadcast LDS
            acc[i][0] = fmaf(xv, wv.x, acc[i][0]);
            acc[i][1] = fmaf(xv, wv.y, acc[i][1]);
            acc[i][2] = fmaf(xv, wv.z, acc[i][2]);
            acc[i][3] = fmaf(xv, wv.w, acc[i][3]);
        }
    }

#pragma unroll
    for (int i = 0; i < 8; i++) {
        int r = row0 + warp * 8 + i;
        if (r < n_rows)
            *(float4*)(g_h + (long)r * DH + lane * 4) =
                make_float4(acc[i][0], acc[i][1], acc[i][2], acc[i][3]);
    }
}

// ---------------- edge scatter: g_agg[dst] += w * g_h[src] ------------------
// one warp per edge; vectorized L2 reduction (red.global.add.v4.f32)
__global__ void scatter_kernel(const int* __restrict__ src,
                               const int* __restrict__ dst,
                               const float* __restrict__ ew) {
    int e = (blockIdx.x * blockDim.x + threadIdx.x) >> 5;
    if (e >= NEDGES) return;
    const int lane = threadIdx.x & 31;
    int s = __ldg(src + e);
    int d = __ldg(dst + e);
    float w = __ldg(ew + e);

    float4 v = *((const float4*)(g_h + (long)s * DH) + lane);
    float4* ap = (float4*)(g_agg + (long)d * DH) + lane;
    asm volatile("red.global.add.v4.f32 [%0], {%1, %2, %3, %4};"
                 :: "l"(ap), "f"(v.x * w), "f"(v.y * w),
                    "f"(v.z * w), "f"(v.w * w)
                 : "memory");
}

// ---------------- column stats of g_agg (sum, sumsq) ------------------------
__global__ void stats_kernel() {
    const int col = threadIdx.x;   // 128 threads
    float s = 0.f, q = 0.f;
    for (int r = blockIdx.x; r < NNODES; r += gridDim.x) {
        float v = g_agg[(long)r * DH + col];
        s += v;
        q = fmaf(v, v, q);
    }
    atomicAdd(&g_stats[col], s);
    atomicAdd(&g_stats[DH + col], q);
}

// ---------------- BN parameters (bias cancels in batch norm) ----------------
__global__ void bnparams_kernel(const float* __restrict__ gamma,
                                const float* __restrict__ beta) {
    int c = threadIdx.x;   // 128 threads
    float mean = g_stats[c] * (1.0f / NNODES);
    float var  = g_stats[DH + c] * (1.0f / NNODES) - mean * mean;
    float scale = gamma[c] * rsqrtf(var + BN_EPS);
    g_scale[c] = scale;
    g_shift[c] = beta[c] - mean * scale;
}

// ---------------- per-src edge-weight sums ----------------------------------
__global__ void srcsum_kernel(const int* __restrict__ src,
                              const float* __restrict__ ew) {
    int e = blockIdx.x * blockDim.x + threadIdx.x;
    if (e < NEDGES) atomicAdd(&g_s[src[e]], ew[e]);
}

// ---------------- t = sum_n s[n] * relu(bn(g_agg[n,:])) ---------------------
__global__ void treduce_kernel() {
    const int col = threadIdx.x;   // 128 threads
    float sc = g_scale[col], sh = g_shift[col];
    float acc = 0.f;
    for (int r = blockIdx.x; r < NNODES; r += gridDim.x) {
        float v = g_agg[(long)r * DH + col];
        v = fmaxf(0.f, fmaf(v, sc, sh));
        acc = fmaf(g_s[r], v, acc);
    }
    atomicAdd(&g_t[col], acc);
}

// ---------------- out = t @ W2 + N * b2 -------------------------------------
__global__ void final_kernel(const float* __restrict__ W2,
                             const float* __restrict__ b2,
                             float* __restrict__ out) {
    int o = threadIdx.x;   // 64 threads
    float acc = (float)NNODES * b2[o];
#pragma unroll 8
    for (int f = 0; f < DH; f++)
        acc = fmaf(g_t[f], W2[f * DOUT + o], acc);
    out[o] = acc;
}

// ---------------- launch ----------------------------------------------------
extern "C" void kernel_launch(void* const* d_in, const int* in_sizes, int n_in,
                              void* d_out, int out_size) {
    const float* nf     = (const float*)d_in[0];
    const int*   ei     = (const int*)  d_in[1];   // [2][E]
    const float* ew     = (const float*)d_in[2];
    const float* W0     = (const float*)d_in[3];
    const float* W1     = (const float*)d_in[5];
    const float* W2     = (const float*)d_in[7];
    const float* b2     = (const float*)d_in[8];
    const float* gamma0 = (const float*)d_in[9];
    const float* beta0  = (const float*)d_in[10];
    const float* gamma1 = (const float*)d_in[11];
    const float* beta1  = (const float*)d_in[12];
    const int* src = ei;
    const int* dst = ei + NEDGES;
    float* out = (float*)d_out;

    cudaFuncSetAttribute(gemm_kernel,
                         cudaFuncAttributeMaxDynamicSharedMemorySize,
                         (int)GEMM_SMEM);

    const int scatter_blocks = (NEDGES * 32 + 255) / 256;

    // ---- layer 0: conv -> BN params
    zero_agg_kernel<<<2048, 256>>>();
    gemm_kernel<<<GRID_GEMM, GEMM_THREADS, GEMM_SMEM>>>(nf, W0, NNODES, 0);
    scatter_kernel<<<scatter_blocks, 256>>>(src, dst, ew);
    zero_small_kernel<<<1, 3 * DH>>>();
    stats_kernel<<<1024, DH>>>();
    bnparams_kernel<<<1, DH>>>(gamma0, beta0);

    // ---- layer 1: (BN+ReLU fused into GEMM load) conv -> BN params
    gemm_kernel<<<GRID_GEMM, GEMM_THREADS, GEMM_SMEM>>>(nullptr, W1, NNODES, 1);
    zero_agg_kernel<<<2048, 256>>>();
    scatter_kernel<<<scatter_blocks, 256>>>(src, dst, ew);
    zero_small_kernel<<<1, 3 * DH>>>();
    stats_kernel<<<1024, DH>>>();
    bnparams_kernel<<<1, DH>>>(gamma1, beta1);

    // ---- layer 2 collapsed: out = (s^T relu(bn(agg1))) @ W2 + N*b2
    zero_s_kernel<<<512, 256>>>();
    srcsum_kernel<<<(NEDGES + 255) / 256, 256>>>(src, ew);
    treduce_kernel<<<1024, DH>>>();
    final_kernel<<<1, DOUT>>>(W2, b2, out);
}

// round 9
// speedup vs baseline: 1.0844x; 1.0844x over previous
#include <cuda_runtime.h>
#include <cuda_bf16.h>

#define NNODES 100000
#define NEDGES 1600000
#define DH 128
#define DOUT 64
#define BN_EPS 1e-5f

#define TM 64
#define GEMM_THREADS 256
// ws: DH*DH floats (64KB) + xd: TM*DH duplicated f32-pairs (64KB)
#define GEMM_SMEM (DH*DH*4 + TM*DH*8)
#define GRID_GEMM ((NNODES + TM - 1) / TM)

// ---------------- device scratch ----------------
__device__ float g_h[(long)NNODES * DH];     // GEMM output (h = xW)
__device__ float g_agg[(long)NNODES * DH];   // aggregation buffer
__device__ float g_s[NNODES];                // per-src edge-weight sums
__device__ float g_stats[2 * DH];            // column sum / sumsq
__device__ float g_scale[DH];                // BN fused scale
__device__ float g_shift[DH];                // BN fused shift
__device__ float g_t[DH];                    // s^T x1
__device__ int   g_rowptr[NNODES + 1];       // CSR by dst
__device__ int   g_cnt[NNODES];              // histogram / fill cursor
__device__ int   g_csr_src[NEDGES];
__device__ float g_csr_w[NEDGES];

#define FFMA2(acc, a, b) \
    asm("fma.rn.f32x2 %0, %1, %2, %0;" : "+l"(acc) : "l"(a), "l"(b))

// ---------------- init: counters, s, stats, t -------------------------------
__global__ void zero_init_kernel() {
    int i = blockIdx.x * blockDim.x + threadIdx.x;
    int stride = gridDim.x * blockDim.x;
    for (int j = i; j < NNODES; j += stride) { g_cnt[j] = 0; g_s[j] = 0.f; }
    if (i < 2 * DH)       g_stats[i] = 0.f;
    else if (i < 3 * DH)  g_t[i - 2 * DH] = 0.f;
}

// ---------------- histogram by dst, fused per-src weight sums ---------------
__global__ void hist_kernel(const int* __restrict__ src,
                            const int* __restrict__ dst,
                            const float* __restrict__ ew) {
    int e = blockIdx.x * blockDim.x + threadIdx.x;
    if (e < NEDGES) {
        atomicAdd(&g_cnt[dst[e]], 1);
        atomicAdd(&g_s[src[e]], ew[e]);
    }
}

// ---------------- exclusive scan of g_cnt -> g_rowptr (single block) --------
__global__ void scan_kernel() {
    __shared__ int ssums[1024];
    const int CH = (NNODES + 1023) / 1024;
    int t = threadIdx.x;
    int base = t * CH;
    int lim = min(base + CH, NNODES);
    int s = 0;
    for (int i = base; i < lim; i++) s += g_cnt[i];
    ssums[t] = s;
    __syncthreads();
    for (int off = 1; off < 1024; off <<= 1) {
        int v = (t >= off) ? ssums[t - off] : 0;
        __syncthreads();
        ssums[t] += v;
        __syncthreads();
    }
    int run = t ? ssums[t - 1] : 0;
    for (int i = base; i < lim; i++) {
        int c = g_cnt[i];
        g_rowptr[i] = run;
        g_cnt[i] = run;          // fill cursor
        run += c;
    }
    if (t == 0) g_rowptr[NNODES] = ssums[1023];
}

// ---------------- fill CSR ---------------------------------------------------
__global__ void fill_kernel(const int* __restrict__ src,
                            const int* __restrict__ dst,
                            const float* __restrict__ ew) {
    int e = blockIdx.x * blockDim.x + threadIdx.x;
    if (e < NEDGES) {
        int pos = atomicAdd(&g_cnt[dst[e]], 1);
        g_csr_src[pos] = src[e];
        g_csr_w[pos]   = ew[e];
    }
}

// ---------------- GEMM: g_h = X @ W via packed fma.rn.f32x2 -----------------
// mode 0: X = Xext (raw); mode 1: X = relu(g_agg*scale+shift)
__global__ void gemm_kernel(const float* __restrict__ Xext,
                            const float* __restrict__ W, int mode) {
    extern __shared__ char sraw[];
    float* ws = (float*)sraw;                                    // w[k][n]
    unsigned long long* xd =
        (unsigned long long*)(sraw + DH * DH * sizeof(float));   // dup x [r][k]

    const int tid = threadIdx.x;
    const float* X = mode ? g_agg : Xext;

    for (int i = tid; i < DH * DH / 4; i += GEMM_THREADS)
        ((float4*)ws)[i] = ((const float4*)W)[i];

    const int row0 = blockIdx.x * TM;
    for (int i = tid; i < TM * DH / 4; i += GEMM_THREADS) {
        int r  = i >> 5;       // DH/4 = 32
        int c4 = i & 31;
        float4 v = make_float4(0.f, 0.f, 0.f, 0.f);
        if (row0 + r < NNODES) {
            v = ((const float4*)(X + (long)(row0 + r) * DH))[c4];
            if (mode) {
                int c = c4 * 4;
                v.x = fmaxf(0.f, fmaf(v.x, g_scale[c + 0], g_shift[c + 0]));
                v.y = fmaxf(0.f, fmaf(v.y, g_scale[c + 1], g_shift[c + 1]));
                v.z = fmaxf(0.f, fmaf(v.z, g_scale[c + 2], g_shift[c + 2]));
                v.w = fmaxf(0.f, fmaf(v.w, g_scale[c + 3], g_shift[c + 3]));
            }
        }
        union { float2 f; unsigned long long u; } p;
        unsigned long long* dp = xd + (long)r * DH + c4 * 4;
        p.f = make_float2(v.x, v.x); dp[0] = p.u;
        p.f = make_float2(v.y, v.y); dp[1] = p.u;
        p.f = make_float2(v.z, v.z); dp[2] = p.u;
        p.f = make_float2(v.w, v.w); dp[3] = p.u;
    }
    __syncthreads();

    const int lane = tid & 31;
    const int warp = tid >> 5;                     // 8 warps x 8 rows
    const unsigned long long* xb = xd + (long)(warp * 8) * DH;

    unsigned long long acc[8][2];
#pragma unroll
    for (int i = 0; i < 8; i++) { acc[i][0] = 0ull; acc[i][1] = 0ull; }

#pragma unroll 4
    for (int k2 = 0; k2 < DH / 2; k2++) {
        ulonglong2 wv0 = *(const ulonglong2*)(ws + (2 * k2) * DH + lane * 4);
        ulonglong2 wv1 = *(const ulonglong2*)(ws + (2 * k2 + 1) * DH + lane * 4);
#pragma unroll
        for (int i = 0; i < 8; i++) {
            ulonglong2 xv = *(const ulonglong2*)(xb + i * DH + 2 * k2);
            FFMA2(acc[i][0], xv.x, wv0.x);
            FFMA2(acc[i][1], xv.x, wv0.y);
            FFMA2(acc[i][0], xv.y, wv1.x);
            FFMA2(acc[i][1], xv.y, wv1.y);
        }
    }

#pragma unroll
    for (int i = 0; i < 8; i++) {
        int r = row0 + warp * 8 + i;
        if (r < NNODES) {
            ulonglong2 o; o.x = acc[i][0]; o.y = acc[i][1];
            *(ulonglong2*)(g_h + (long)r * DH + lane * 4) = o;
        }
    }
}

// ---------------- CSR gather-aggregate with fused column stats --------------
// one warp per node; lane owns 4 columns; stats accumulated in registers
__global__ void gather_kernel() {
    __shared__ float sred[8][DH];
    __shared__ float sred2[8][DH];
    const int tid = threadIdx.x;
    const int lane = tid & 31;
    const int warp = tid >> 5;

    float4 lsum = make_float4(0.f, 0.f, 0.f, 0.f);
    float4 lsq  = make_float4(0.f, 0.f, 0.f, 0.f);

    for (int n = blockIdx.x * 8 + warp; n < NNODES; n += gridDim.x * 8) {
        int beg = g_rowptr[n], end = g_rowptr[n + 1];
        float4 acc = make_float4(0.f, 0.f, 0.f, 0.f);
        int j = beg;
        for (; j + 2 <= end; j += 2) {
            int   s0 = g_csr_src[j],   s1 = g_csr_src[j + 1];
            float w0 = g_csr_w[j],     w1 = g_csr_w[j + 1];
            float4 h0 = ((const float4*)(g_h + (long)s0 * DH))[lane];
            float4 h1 = ((const float4*)(g_h + (long)s1 * DH))[lane];
            acc.x = fmaf(w0, h0.x, acc.x); acc.y = fmaf(w0, h0.y, acc.y);
            acc.z = fmaf(w0, h0.z, acc.z); acc.w = fmaf(w0, h0.w, acc.w);
            acc.x = fmaf(w1, h1.x, acc.x); acc.y = fmaf(w1, h1.y, acc.y);
            acc.z = fmaf(w1, h1.z, acc.z); acc.w = fmaf(w1, h1.w, acc.w);
        }
        if (j < end) {
            int s0 = g_csr_src[j]; float w0 = g_csr_w[j];
            float4 h0 = ((const float4*)(g_h + (long)s0 * DH))[lane];
            acc.x = fmaf(w0, h0.x, acc.x); acc.y = fmaf(w0, h0.y, acc.y);
            acc.z = fmaf(w0, h0.z, acc.z); acc.w = fmaf(w0, h0.w, acc.w);
        }
        ((float4*)(g_agg + (long)n * DH))[lane] = acc;

        lsum.x += acc.x; lsum.y += acc.y; lsum.z += acc.z; lsum.w += acc.w;
        lsq.x = fmaf(acc.x, acc.x, lsq.x); lsq.y = fmaf(acc.y, acc.y, lsq.y);
        lsq.z = fmaf(acc.z, acc.z, lsq.z); lsq.w = fmaf(acc.w, acc.w, lsq.w);
    }

    sred[warp][lane * 4 + 0] = lsum.x;  sred2[warp][lane * 4 + 0] = lsq.x;
    sred[warp][lane * 4 + 1] = lsum.y;  sred2[warp][lane * 4 + 1] = lsq.y;
    sred[warp][lane * 4 + 2] = lsum.z;  sred2[warp][lane * 4 + 2] = lsq.z;
    sred[warp][lane * 4 + 3] = lsum.w;  sred2[warp][lane * 4 + 3] = lsq.w;
    __syncthreads();
    if (tid < DH) {
        float a = 0.f, b = 0.f;
#pragma unroll
        for (int w = 0; w < 8; w++) { a += sred[w][tid]; b += sred2[w][tid]; }
        atomicAdd(&g_stats[tid], a);
        atomicAdd(&g_stats[DH + tid], b);
    }
}

// ---------------- BN parameters (conv bias cancels in BN); self-resets ------
__global__ void bnparams_kernel(const float* __restrict__ gamma,
                                const float* __restrict__ beta) {
    int c = threadIdx.x;   // 128 threads
    float mean = g_stats[c] * (1.0f / NNODES);
    float var  = g_stats[DH + c] * (1.0f / NNODES) - mean * mean;
    float sc   = gamma[c] * rsqrtf(var + BN_EPS);
    g_scale[c] = sc;
    g_shift[c] = beta[c] - mean * sc;
    g_stats[c] = 0.f;          // reset for the next layer's stats
    g_stats[DH + c] = 0.f;
}

// ---------------- t = sum_n s[n] * relu(bn(g_agg[n,:])) ---------------------
__global__ void treduce_kernel() {
    const int col = threadIdx.x;   // 128 threads
    float sc = g_scale[col], sh = g_shift[col];
    float acc = 0.f;
    for (int r = blockIdx.x; r < NNODES; r += gridDim.x) {
        float v = g_agg[(long)r * DH + col];
        v = fmaxf(0.f, fmaf(v, sc, sh));
        acc = fmaf(g_s[r], v, acc);
    }
    atomicAdd(&g_t[col], acc);
}

// ---------------- out = t @ W2 + N * b2 -------------------------------------
__global__ void final_kernel(const float* __restrict__ W2,
                             const float* __restrict__ b2,
                             float* __restrict__ out) {
    int o = threadIdx.x;   // 64 threads
    float acc = (float)NNODES * b2[o];
#pragma unroll 8
    for (int f = 0; f < DH; f++)
        acc = fmaf(g_t[f], W2[f * DOUT + o], acc);
    out[o] = acc;
}

// ---------------- launch ----------------------------------------------------
extern "C" void kernel_launch(void* const* d_in, const int* in_sizes, int n_in,
                              void* d_out, int out_size) {
    const float* nf     = (const float*)d_in[0];
    const int*   ei     = (const int*)  d_in[1];   // [2][E]
    const float* ew     = (const float*)d_in[2];
    const float* W0     = (const float*)d_in[3];
    const float* W1     = (const float*)d_in[5];
    const float* W2     = (const float*)d_in[7];
    const float* b2     = (const float*)d_in[8];
    const float* gamma0 = (const float*)d_in[9];
    const float* beta0  = (const float*)d_in[10];
    const float* gamma1 = (const float*)d_in[11];
    const float* beta1  = (const float*)d_in[12];
    const int* src = ei;
    const int* dst = ei + NEDGES;
    float* out = (float*)d_out;

    cudaFuncSetAttribute(gemm_kernel,
                         cudaFuncAttributeMaxDynamicSharedMemorySize,
                         (int)GEMM_SMEM);

    // ---- CSR build (reused by both aggregation layers) + src weight sums
    zero_init_kernel<<<(NNODES + 255) / 256, 256>>>();
    hist_kernel<<<(NEDGES + 255) / 256, 256>>>(src, dst, ew);
    scan_kernel<<<1, 1024>>>();
    fill_kernel<<<(NEDGES + 255) / 256, 256>>>(src, dst, ew);

    // ---- layer 0: GEMM -> CSR gather (stats fused) -> BN params
    gemm_kernel<<<GRID_GEMM, GEMM_THREADS, GEMM_SMEM>>>(nf, W0, 0);
    gather_kernel<<<2048, 256>>>();
    bnparams_kernel<<<1, DH>>>(gamma0, beta0);

    // ---- layer 1: BN+ReLU fused into GEMM load
    gemm_kernel<<<GRID_GEMM, GEMM_THREADS, GEMM_SMEM>>>(nullptr, W1, 1);
    gather_kernel<<<2048, 256>>>();
    bnparams_kernel<<<1, DH>>>(gamma1, beta1);

    // ---- layer 2 collapsed: out = (s^T relu(bn(agg1))) @ W2 + N*b2
    treduce_kernel<<<1024, DH>>>();
    final_kernel<<<1, DOUT>>>(W2, b2, out);
}

// round 12
// speedup vs baseline: 1.4141x; 1.3040x over previous
#include <cuda_runtime.h>
#include <cuda_bf16.h>

#define NNODES 100000
#define NEDGES 1600000
#define DH 128
#define DOUT 64
#define BN_EPS 1e-5f

#define TM 64
#define GEMM_THREADS 256
#define XS_STRIDE 132                 // 64 rows  (A tile), bank-spread pad
#define WS_STRIDE 136                 // 128 rows (B tile), bank-spread pad
#define GEMM_SMEM ((DH * WS_STRIDE + TM * XS_STRIDE) * 4)   // ~103.4 KB
#define GRID_GEMM ((NNODES + TM - 1) / TM)

// ---------------- device scratch ----------------
__device__ float g_h[(long)NNODES * DH];     // GEMM output (h = xW)
__device__ float g_agg[(long)NNODES * DH];   // aggregation buffer
__device__ float g_s[NNODES];                // per-src edge-weight sums
__device__ float g_stats[2 * DH];            // column sum / sumsq
__device__ float g_scale[DH];                // BN fused scale
__device__ float g_shift[DH];                // BN fused shift
__device__ float g_t[DH];                    // s^T x1
__device__ int   g_rowptr[NNODES + 1];       // CSR by dst
__device__ int   g_cnt[NNODES];              // histogram / fill cursor
__device__ int   g_csr_src[NEDGES];
__device__ float g_csr_w[NEDGES];

__device__ __forceinline__ unsigned tf32_of(float f) {
    unsigned r;
    asm("cvt.rna.tf32.f32 %0, %1;" : "=r"(r) : "f"(f));
    return r;
}

#define MMA_TF32(d, a, b)                                                    \
    asm volatile(                                                            \
        "mma.sync.aligned.m16n8k8.row.col.f32.tf32.tf32.f32 "                \
        "{%0,%1,%2,%3}, {%4,%5,%6,%7}, {%8,%9}, {%0,%1,%2,%3};"              \
        : "+f"((d)[0]), "+f"((d)[1]), "+f"((d)[2]), "+f"((d)[3])             \
        : "r"((a)[0]), "r"((a)[1]), "r"((a)[2]), "r"((a)[3]),                \
          "r"((b)[0]), "r"((b)[1]))

// ---------------- init: counters, s, stats, t -------------------------------
__global__ void zero_init_kernel() {
    int i = blockIdx.x * blockDim.x + threadIdx.x;
    int stride = gridDim.x * blockDim.x;
    for (int j = i; j < NNODES; j += stride) { g_cnt[j] = 0; g_s[j] = 0.f; }
    if (i < 2 * DH)       g_stats[i] = 0.f;
    else if (i < 3 * DH)  g_t[i - 2 * DH] = 0.f;
}

// ---------------- histogram by dst, fused per-src weight sums ---------------
__global__ void hist_kernel(const int* __restrict__ src,
                            const int* __restrict__ dst,
                            const float* __restrict__ ew) {
    int e = blockIdx.x * blockDim.x + threadIdx.x;
    if (e < NEDGES) {
        atomicAdd(&g_cnt[dst[e]], 1);
        atomicAdd(&g_s[src[e]], ew[e]);
    }
}

// ---------------- exclusive scan of g_cnt -> g_rowptr (single block) --------
__global__ void scan_kernel() {
    __shared__ int ssums[1024];
    const int CH = (NNODES + 1023) / 1024;
    int t = threadIdx.x;
    int base = t * CH;
    int lim = min(base + CH, NNODES);
    int s = 0;
    for (int i = base; i < lim; i++) s += g_cnt[i];
    ssums[t] = s;
    __syncthreads();
    for (int off = 1; off < 1024; off <<= 1) {
        int v = (t >= off) ? ssums[t - off] : 0;
        __syncthreads();
        ssums[t] += v;
        __syncthreads();
    }
    int run = t ? ssums[t - 1] : 0;
    for (int i = base; i < lim; i++) {
        int c = g_cnt[i];
        g_rowptr[i] = run;
        g_cnt[i] = run;          // fill cursor
        run += c;
    }
    if (t == 0) g_rowptr[NNODES] = ssums[1023];
}

// ---------------- fill CSR ---------------------------------------------------
__global__ void fill_kernel(const int* __restrict__ src,
                            const int* __restrict__ dst,
                            const float* __restrict__ ew) {
    int e = blockIdx.x * blockDim.x + threadIdx.x;
    if (e < NEDGES) {
        int pos = atomicAdd(&g_cnt[dst[e]], 1);
        g_csr_src[pos] = src[e];
        g_csr_w[pos]   = ew[e];
    }
}

// ---------------- GEMM: g_h = X @ W via TF32 tensor-core mma ----------------
// mode 0: X = Xext (raw); mode 1: X = relu(g_agg*scale+shift)
// Block tile 64x128, K=128. Warp tile 32 rows x 32 cols (2 m-tiles x 4 n-tiles).
__global__ void gemm_kernel(const float* __restrict__ Xext,
                            const float* __restrict__ W, int mode) {
    extern __shared__ unsigned smem_u[];
    unsigned* ws = smem_u;                        // [128][WS_STRIDE] tf32
    unsigned* xs = smem_u + DH * WS_STRIDE;       // [64][XS_STRIDE]  tf32

    const int tid = threadIdx.x;
    const float* X = mode ? g_agg : Xext;

    // ---- stage W (k-major) as tf32
    for (int i = tid; i < DH * DH / 4; i += GEMM_THREADS) {
        int k  = i >> 5;          // 32 float4 per row
        int c4 = (i & 31) << 2;
        float4 v = ((const float4*)W)[i];
        uint4 o;
        o.x = tf32_of(v.x); o.y = tf32_of(v.y);
        o.z = tf32_of(v.z); o.w = tf32_of(v.w);
        *(uint4*)(ws + k * WS_STRIDE + c4) = o;
    }

    // ---- stage X tile (with fused BN+ReLU for mode 1) as tf32
    const int row0 = blockIdx.x * TM;
    for (int i = tid; i < TM * DH / 4; i += GEMM_THREADS) {
        int r  = i >> 5;
        int c4 = (i & 31) << 2;
        float4 v = make_float4(0.f, 0.f, 0.f, 0.f);
        if (row0 + r < NNODES) {
            v = *(const float4*)(X + (long)(row0 + r) * DH + c4);
            if (mode) {
                v.x = fmaxf(0.f, fmaf(v.x, g_scale[c4 + 0], g_shift[c4 + 0]));
                v.y = fmaxf(0.f, fmaf(v.y, g_scale[c4 + 1], g_shift[c4 + 1]));
                v.z = fmaxf(0.f, fmaf(v.z, g_scale[c4 + 2], g_shift[c4 + 2]));
                v.w = fmaxf(0.f, fmaf(v.w, g_scale[c4 + 3], g_shift[c4 + 3]));
            }
        }
        uint4 o;
        o.x = tf32_of(v.x); o.y = tf32_of(v.y);
        o.z = tf32_of(v.z); o.w = tf32_of(v.w);
        *(uint4*)(xs + r * XS_STRIDE + c4) = o;
    }
    __syncthreads();

    const int lane = tid & 31;
    const int warp = tid >> 5;
    const int mrow = (warp & 1) * 32;     // row offset of this warp's 32 rows
    const int ncol = (warp >> 1) * 32;    // col offset of this warp's 32 cols

    float acc[2][4][4];
#pragma unroll
    for (int mi = 0; mi < 2; mi++)
#pragma unroll
        for (int ni = 0; ni < 4; ni++)
#pragma unroll
            for (int j = 0; j < 4; j++) acc[mi][ni][j] = 0.f;

    const int ar = mrow + (lane >> 2);    // A fragment row (within tile)
    const int ak = lane & 3;              // A fragment col (within k-step)
    const int bn = ncol + (lane >> 2);    // B fragment col
    const int bk = lane & 3;              // B fragment row (within k-step)

#pragma unroll 4
    for (int k0 = 0; k0 < DH; k0 += 8) {
        unsigned a[2][4], b[4][2];
#pragma unroll
        for (int mi = 0; mi < 2; mi++) {
            const unsigned* ab = xs + (ar + 16 * mi) * XS_STRIDE + k0 + ak;
            a[mi][0] = ab[0];
            a[mi][1] = ab[8 * XS_STRIDE];
            a[mi][2] = ab[4];
            a[mi][3] = ab[8 * XS_STRIDE + 4];
        }
#pragma unroll
        for (int ni = 0; ni < 4; ni++) {
            const unsigned* bb = ws + (k0 + bk) * WS_STRIDE + bn + 8 * ni;
            b[ni][0] = bb[0];
            b[ni][1] = bb[4 * WS_STRIDE];
        }
#pragma unroll
        for (int mi = 0; mi < 2; mi++)
#pragma unroll
            for (int ni = 0; ni < 4; ni++)
                MMA_TF32(acc[mi][ni], a[mi], b[ni]);
    }

    // ---- epilogue: c0,c1 at (r, 2q),(r, 2q+1); c2,c3 at (r+8, ...)
#pragma unroll
    for (int mi = 0; mi < 2; mi++) {
        int r0 = row0 + mrow + 16 * mi + (lane >> 2);
        int r1 = r0 + 8;
#pragma unroll
        for (int ni = 0; ni < 4; ni++) {
            int cc = ncol + 8 * ni + 2 * (lane & 3);
            if (r0 < NNODES)
                *(float2*)(g_h + (long)r0 * DH + cc) =
                    make_float2(acc[mi][ni][0], acc[mi][ni][1]);
            if (r1 < NNODES)
                *(float2*)(g_h + (long)r1 * DH + cc) =
                    make_float2(acc[mi][ni][2], acc[mi][ni][3]);
        }
    }
}

// ---------------- CSR gather-aggregate with fused column stats --------------
// one warp per node; lane owns 4 columns; stats accumulated in registers
__global__ void gather_kernel() {
    __shared__ float sred[8][DH];
    __shared__ float sred2[8][DH];
    const int tid = threadIdx.x;
    const int lane = tid & 31;
    const int warp = tid >> 5;

    float4 lsum = make_float4(0.f, 0.f, 0.f, 0.f);
    float4 lsq  = make_float4(0.f, 0.f, 0.f, 0.f);

    for (int n = blockIdx.x * 8 + warp; n < NNODES; n += gridDim.x * 8) {
        int beg = g_rowptr[n], end = g_rowptr[n + 1];
        float4 acc = make_float4(0.f, 0.f, 0.f, 0.f);
        int j = beg;
        for (; j + 2 <= end; j += 2) {
            int   s0 = g_csr_src[j],   s1 = g_csr_src[j + 1];
            float w0 = g_csr_w[j],     w1 = g_csr_w[j + 1];
            float4 h0 = ((const float4*)(g_h + (long)s0 * DH))[lane];
            float4 h1 = ((const float4*)(g_h + (long)s1 * DH))[lane];
            acc.x = fmaf(w0, h0.x, acc.x); acc.y = fmaf(w0, h0.y, acc.y);
            acc.z = fmaf(w0, h0.z, acc.z); acc.w = fmaf(w0, h0.w, acc.w);
            acc.x = fmaf(w1, h1.x, acc.x); acc.y = fmaf(w1, h1.y, acc.y);
            acc.z = fmaf(w1, h1.z, acc.z); acc.w = fmaf(w1, h1.w, acc.w);
        }
        if (j < end) {
            int s0 = g_csr_src[j]; float w0 = g_csr_w[j];
            float4 h0 = ((const float4*)(g_h + (long)s0 * DH))[lane];
            acc.x = fmaf(w0, h0.x, acc.x); acc.y = fmaf(w0, h0.y, acc.y);
            acc.z = fmaf(w0, h0.z, acc.z); acc.w = fmaf(w0, h0.w, acc.w);
        }
        ((float4*)(g_agg + (long)n * DH))[lane] = acc;

        lsum.x += acc.x; lsum.y += acc.y; lsum.z += acc.z; lsum.w += acc.w;
        lsq.x = fmaf(acc.x, acc.x, lsq.x); lsq.y = fmaf(acc.y, acc.y, lsq.y);
        lsq.z = fmaf(acc.z, acc.z, lsq.z); lsq.w = fmaf(acc.w, acc.w, lsq.w);
    }

    sred[warp][lane * 4 + 0] = lsum.x;  sred2[warp][lane * 4 + 0] = lsq.x;
    sred[warp][lane * 4 + 1] = lsum.y;  sred2[warp][lane * 4 + 1] = lsq.y;
    sred[warp][lane * 4 + 2] = lsum.z;  sred2[warp][lane * 4 + 2] = lsq.z;
    sred[warp][lane * 4 + 3] = lsum.w;  sred2[warp][lane * 4 + 3] = lsq.w;
    __syncthreads();
    if (tid < DH) {
        float a = 0.f, b = 0.f;
#pragma unroll
        for (int w = 0; w < 8; w++) { a += sred[w][tid]; b += sred2[w][tid]; }
        atomicAdd(&g_stats[tid], a);
        atomicAdd(&g_stats[DH + tid], b);
    }
}

// ---------------- BN parameters (conv bias cancels in BN); self-resets ------
__global__ void bnparams_kernel(const float* __restrict__ gamma,
                                const float* __restrict__ beta) {
    int c = threadIdx.x;   // 128 threads
    float mean = g_stats[c] * (1.0f / NNODES);
    float var  = g_stats[DH + c] * (1.0f / NNODES) - mean * mean;
    float sc   = gamma[c] * rsqrtf(var + BN_EPS);
    g_scale[c] = sc;
    g_shift[c] = beta[c] - mean * sc;
    g_stats[c] = 0.f;          // reset for the next layer's stats
    g_stats[DH + c] = 0.f;
}

// ---------------- t = sum_n s[n] * relu(bn(g_agg[n,:])) ---------------------
__global__ void treduce_kernel() {
    const int col = threadIdx.x;   // 128 threads
    float sc = g_scale[col], sh = g_shift[col];
    float acc = 0.f;
    for (int r = blockIdx.x; r < NNODES; r += gridDim.x) {
        float v = g_agg[(long)r * DH + col];
        v = fmaxf(0.f, fmaf(v, sc, sh));
        acc = fmaf(g_s[r], v, acc);
    }
    atomicAdd(&g_t[col], acc);
}

// ---------------- out = t @ W2 + N * b2 -------------------------------------
__global__ void final_kernel(const float* __restrict__ W2,
                             const float* __restrict__ b2,
                             float* __restrict__ out) {
    int o = threadIdx.x;   // 64 threads
    float acc = (float)NNODES * b2[o];
#pragma unroll 8
    for (int f = 0; f < DH; f++)
        acc = fmaf(g_t[f], W2[f * DOUT + o], acc);
    out[o] = acc;
}

// ---------------- launch ----------------------------------------------------
extern "C" void kernel_launch(void* const* d_in, const int* in_sizes, int n_in,
                              void* d_out, int out_size) {
    const float* nf     = (const float*)d_in[0];
    const int*   ei     = (const int*)  d_in[1];   // [2][E]
    const float* ew     = (const float*)d_in[2];
    const float* W0     = (const float*)d_in[3];
    const float* W1     = (const float*)d_in[5];
    const float* W2     = (const float*)d_in[7];
    const float* b2     = (const float*)d_in[8];
    const float* gamma0 = (const float*)d_in[9];
    const float* beta0  = (const float*)d_in[10];
    const float* gamma1 = (const float*)d_in[11];
    const float* beta1  = (const float*)d_in[12];
    const int* src = ei;
    const int* dst = ei + NEDGES;
    float* out = (float*)d_out;

    cudaFuncSetAttribute(gemm_kernel,
                         cudaFuncAttributeMaxDynamicSharedMemorySize,
                         (int)GEMM_SMEM);

    // ---- CSR build (reused by both aggregation layers) + src weight sums
    zero_init_kernel<<<(NNODES + 255) / 256, 256>>>();
    hist_kernel<<<(NEDGES + 255) / 256, 256>>>(src, dst, ew);
    scan_kernel<<<1, 1024>>>();
    fill_kernel<<<(NEDGES + 255) / 256, 256>>>(src, dst, ew);

    // ---- layer 0: TF32 GEMM -> CSR gather (stats fused) -> BN params
    gemm_kernel<<<GRID_GEMM, GEMM_THREADS, GEMM_SMEM>>>(nf, W0, 0);
    gather_kernel<<<2048, 256>>>();
    bnparams_kernel<<<1, DH>>>(gamma0, beta0);

    // ---- layer 1: BN+ReLU fused into GEMM tile load
    gemm_kernel<<<GRID_GEMM, GEMM_THREADS, GEMM_SMEM>>>(nullptr, W1, 1);
    gather_kernel<<<2048, 256>>>();
    bnparams_kernel<<<1, DH>>>(gamma1, beta1);

    // ---- layer 2 collapsed: out = (s^T relu(bn(agg1))) @ W2 + N*b2
    treduce_kernel<<<1024, DH>>>();
    final_kernel<<<1, DOUT>>>(W2, b2, out);
}